// round 1
// baseline (speedup 1.0000x reference)
#include <cuda_runtime.h>
#include <cstdint>

// Problem constants (fixed by setup_inputs)
#define BB     8192
#define SSAMP  8
#define HH     256
#define SD     9
#define AD     7
#define IN2    16
#define HOR    4
#define TILE_M 64
#define KT     32

// Scratch (device globals — no allocation allowed)
__device__ float g_cand[SSAMP * BB * AD];   // (S,B,7) clipped candidates
__device__ float g_cost[SSAMP * BB];        // (S,B) total rollout cost

// Shared-memory layout (floats) for rollout kernel
// s_w1:4096 | s_b1:256 | s_b2:256 | s_w3t:2304 | s_b3:16 | s_tgt:192 |
// s_inp:1024 | s_h:16384 | s_wt:16384  => 40912 floats = 163648 bytes
#define SMEM_FLOATS 40912
#define SMEM_BYTES  (SMEM_FLOATS * 4)

struct F4 { float v[4]; };

__device__ __forceinline__ F4 ld4s(const float* p) {
    float4 t = *reinterpret_cast<const float4*>(p);
    F4 r; r.v[0] = t.x; r.v[1] = t.y; r.v[2] = t.z; r.v[3] = t.w;
    return r;
}

__device__ __forceinline__ void cp16(float* smem_dst, const float* gsrc) {
    uint32_t d = (uint32_t)__cvta_generic_to_shared(smem_dst);
    asm volatile("cp.async.cg.shared.global [%0], [%1], 16;\n" :: "r"(d), "l"(gsrc));
}
__device__ __forceinline__ void cp_commit() {
    asm volatile("cp.async.commit_group;\n" ::);
}
__device__ __forceinline__ void cp_wait1() {
    asm volatile("cp.async.wait_group 1;\n" ::);
}
__device__ __forceinline__ void cp_wait0() {
    asm volatile("cp.async.wait_group 0;\n" ::);
}

// ---------------------------------------------------------------------------
// Kernel 1: action proposal. One warp per batch row b.
//   base = tanh(relu(x@pw1+pb1)@pw2+pb2); cand[s][b] = clip(base + 0.2*noise)
// ---------------------------------------------------------------------------
__global__ __launch_bounds__(256) void proposal_kernel(
    const float* __restrict__ state, const float* __restrict__ proprio,
    const float* __restrict__ noise,
    const float* __restrict__ pw1, const float* __restrict__ pb1,
    const float* __restrict__ pw2, const float* __restrict__ pb2)
{
    int warp = threadIdx.x >> 5, lane = threadIdx.x & 31;
    int b = blockIdx.x * 8 + warp;

    float h[8];
#pragma unroll
    for (int c = 0; c < 8; c++) h[c] = pb1[lane + 32 * c];
#pragma unroll
    for (int i = 0; i < 11; i++) {
        float xi = (i < 9) ? state[b * 9 + i] : proprio[b * 2 + (i - 9)];
#pragma unroll
        for (int c = 0; c < 8; c++)
            h[c] = fmaf(xi, pw1[i * 256 + lane + 32 * c], h[c]);
    }
#pragma unroll
    for (int c = 0; c < 8; c++) h[c] = fmaxf(h[c], 0.0f);

    float p[7];
#pragma unroll
    for (int a = 0; a < 7; a++) {
        float s = 0.0f;
#pragma unroll
        for (int c = 0; c < 8; c++)
            s = fmaf(h[c], pw2[(lane + 32 * c) * 7 + a], s);
        p[a] = s;
    }
#pragma unroll
    for (int off = 16; off >= 1; off >>= 1) {
#pragma unroll
        for (int a = 0; a < 7; a++)
            p[a] += __shfl_xor_sync(0xffffffffu, p[a], off);
    }

    if (lane < 7) {
        float base = tanhf(p[lane] + pb2[lane]);
#pragma unroll
        for (int s = 0; s < SSAMP; s++) {
            float v = base + 0.2f * noise[(s * BB + b) * 7 + lane];
            v = fminf(fmaxf(v, -1.0f), 1.0f);
            g_cand[(s * BB + b) * 7 + lane] = v;
        }
    }
}

// ---------------------------------------------------------------------------
// Kernel 2: rollout. 1 CTA = 64 samples (single s, 64 consecutive b).
// 256 threads, 8x8 register tile each. w2 streamed through smem (cp.async,
// double-buffered 32-row tiles). h / inp / cost are warp-private rows.
// ---------------------------------------------------------------------------
__global__ __launch_bounds__(256, 1) void rollout_kernel(
    const float* __restrict__ state, const float* __restrict__ target,
    const float* __restrict__ w1, const float* __restrict__ b1,
    const float* __restrict__ w2, const float* __restrict__ b2,
    const float* __restrict__ w3, const float* __restrict__ b3)
{
    extern __shared__ float smem[];
    float* s_w1  = smem;              // [16][256]
    float* s_b1  = s_w1 + 4096;       // [256]
    float* s_b2  = s_b1 + 256;        // [256]
    float* s_w3t = s_b2 + 256;        // [9][256]  (transposed w3)
    float* s_b3  = s_w3t + 2304;      // [16]
    float* s_tgt = s_b3 + 16;         // [64][3]
    float* s_inp = s_tgt + 192;       // [64][16]  cols 0..8=sim, 9..15=cand
    float* s_h   = s_inp + 1024;      // [64][256]
    float* s_wt  = s_h + 16384;       // [2][32][256]

    const int tid = threadIdx.x;
    const int sample0 = blockIdx.x * TILE_M;
    const int s_idx = sample0 / BB;
    const int b0 = sample0 % BB;

    // ---- cooperative init ----
    {
        const float4* w1v = reinterpret_cast<const float4*>(w1);
        float4* sw1v = reinterpret_cast<float4*>(s_w1);
        for (int i = tid; i < 1024; i += 256) sw1v[i] = w1v[i];
        s_b1[tid] = b1[tid];
        s_b2[tid] = b2[tid];
        for (int i = tid; i < 2304; i += 256) {
            int j = i / 9, d = i % 9;
            s_w3t[d * 256 + j] = w3[i];
        }
        if (tid < 9) s_b3[tid] = b3[tid];
        if (tid < 192) s_tgt[tid] = target[b0 * 3 + tid];
        for (int i = tid; i < 576; i += 256) {
            int m = i / 9, d = i % 9;
            s_inp[m * 16 + d] = state[(b0 + m) * 9 + d];
        }
        for (int i = tid; i < 448; i += 256) {
            int m = i / 7, a = i % 7;
            s_inp[m * 16 + 9 + a] = g_cand[(s_idx * BB + b0 + m) * 7 + a];
        }
    }
    __syncthreads();

    const int mi = tid >> 5;          // 0..7  (m-group / warp id)
    const int ji = tid & 31;          // 0..31 (lane)
    const int J0 = ji * 4;            // first 4-wide j slice
    const int J1 = 128 + ji * 4;      // second 4-wide j slice
    const int mrow = mi * 8;

    float cm[8];
#pragma unroll
    for (int mm = 0; mm < 8; mm++) cm[mm] = 0.0f;

    float acc[8][8];

    for (int step = 0; step < HOR; step++) {
        // ---- prefetch w2 tile 0 for this step ----
        {
            const float4* src = reinterpret_cast<const float4*>(w2);
            float4* dst = reinterpret_cast<float4*>(s_wt);
#pragma unroll
            for (int i = 0; i < 8; i++) {
                int idx = tid + i * 256;
                cp16(reinterpret_cast<float*>(dst + idx),
                     reinterpret_cast<const float*>(src + idx));
            }
            cp_commit();
        }

        // ================= GEMM1: h1 = relu(inp @ w1 + b1) =================
        {
            F4 bA = ld4s(s_b1 + J0), bB = ld4s(s_b1 + J1);
#pragma unroll
            for (int mm = 0; mm < 8; mm++) {
#pragma unroll
                for (int c = 0; c < 4; c++) { acc[mm][c] = bA.v[c]; acc[mm][4 + c] = bB.v[c]; }
            }
#pragma unroll 2
            for (int k0 = 0; k0 < 16; k0 += 4) {
                F4 wA[4], wB[4];
#pragma unroll
                for (int t = 0; t < 4; t++) {
                    wA[t] = ld4s(s_w1 + (k0 + t) * 256 + J0);
                    wB[t] = ld4s(s_w1 + (k0 + t) * 256 + J1);
                }
#pragma unroll
                for (int mm = 0; mm < 8; mm++) {
                    F4 iv = ld4s(s_inp + (mrow + mm) * 16 + k0);
#pragma unroll
                    for (int t = 0; t < 4; t++) {
#pragma unroll
                        for (int c = 0; c < 4; c++) {
                            acc[mm][c]     = fmaf(iv.v[t], wA[t].v[c], acc[mm][c]);
                            acc[mm][4 + c] = fmaf(iv.v[t], wB[t].v[c], acc[mm][4 + c]);
                        }
                    }
                }
            }
            // relu + store h1 (warp-private rows)
#pragma unroll
            for (int mm = 0; mm < 8; mm++) {
                float4 st0, st1;
                st0.x = fmaxf(acc[mm][0], 0.0f); st0.y = fmaxf(acc[mm][1], 0.0f);
                st0.z = fmaxf(acc[mm][2], 0.0f); st0.w = fmaxf(acc[mm][3], 0.0f);
                st1.x = fmaxf(acc[mm][4], 0.0f); st1.y = fmaxf(acc[mm][5], 0.0f);
                st1.z = fmaxf(acc[mm][6], 0.0f); st1.w = fmaxf(acc[mm][7], 0.0f);
                *reinterpret_cast<float4*>(&s_h[(mrow + mm) * 256 + J0]) = st0;
                *reinterpret_cast<float4*>(&s_h[(mrow + mm) * 256 + J1]) = st1;
            }
        }

        // ================= GEMM2: z2 = h1 @ w2 + b2 (k-tiled) ==============
        {
            F4 bA = ld4s(s_b2 + J0), bB = ld4s(s_b2 + J1);
#pragma unroll
            for (int mm = 0; mm < 8; mm++) {
#pragma unroll
                for (int c = 0; c < 4; c++) { acc[mm][c] = bA.v[c]; acc[mm][4 + c] = bB.v[c]; }
            }

            for (int kt = 0; kt < 8; kt++) {
                if (kt < 7) {
                    const float4* src = reinterpret_cast<const float4*>(w2 + (kt + 1) * KT * 256);
                    float4* dst = reinterpret_cast<float4*>(s_wt + ((kt + 1) & 1) * 8192);
#pragma unroll
                    for (int i = 0; i < 8; i++) {
                        int idx = tid + i * 256;
                        cp16(reinterpret_cast<float*>(dst + idx),
                             reinterpret_cast<const float*>(src + idx));
                    }
                    cp_commit();
                    cp_wait1();
                } else {
                    cp_wait0();
                }
                __syncthreads();   // tile kt visible to all

                const float* W = s_wt + (kt & 1) * 8192;
                const float* Hbase = s_h + mrow * 256 + kt * KT;
#pragma unroll 2
                for (int kk = 0; kk < KT; kk += 4) {
                    F4 wA[4], wB[4];
#pragma unroll
                    for (int t = 0; t < 4; t++) {
                        wA[t] = ld4s(W + (kk + t) * 256 + J0);
                        wB[t] = ld4s(W + (kk + t) * 256 + J1);
                    }
#pragma unroll
                    for (int mm = 0; mm < 8; mm++) {
                        F4 hv = ld4s(Hbase + mm * 256 + kk);
#pragma unroll
                        for (int t = 0; t < 4; t++) {
#pragma unroll
                            for (int c = 0; c < 4; c++) {
                                acc[mm][c]     = fmaf(hv.v[t], wA[t].v[c], acc[mm][c]);
                                acc[mm][4 + c] = fmaf(hv.v[t], wB[t].v[c], acc[mm][4 + c]);
                            }
                        }
                    }
                }
                __syncthreads();   // safe to overwrite this buffer next iter
            }
        }

        // ============ GEMM3: sim = relu(z2) @ w3 + b3 ; cost accum =========
        {
#pragma unroll
            for (int mm = 0; mm < 8; mm++)
#pragma unroll
                for (int c = 0; c < 8; c++) acc[mm][c] = fmaxf(acc[mm][c], 0.0f);

            for (int d = 0; d < 9; d++) {
                F4 wA = ld4s(s_w3t + d * 256 + J0);
                F4 wB = ld4s(s_w3t + d * 256 + J1);
                float pd[8];
#pragma unroll
                for (int mm = 0; mm < 8; mm++) {
                    float s = 0.0f;
#pragma unroll
                    for (int c = 0; c < 4; c++) {
                        s = fmaf(acc[mm][c], wA.v[c], s);
                        s = fmaf(acc[mm][4 + c], wB.v[c], s);
                    }
                    pd[mm] = s;
                }
#pragma unroll
                for (int off = 16; off >= 1; off >>= 1) {
#pragma unroll
                    for (int mm = 0; mm < 8; mm++)
                        pd[mm] += __shfl_xor_sync(0xffffffffu, pd[mm], off);
                }
                if (ji == 0) {
#pragma unroll
                    for (int mm = 0; mm < 8; mm++) {
                        float sv = pd[mm] + s_b3[d];
                        s_inp[(mrow + mm) * 16 + d] = sv;
                        if (d < 3) {
                            float t = sv - s_tgt[(mrow + mm) * 3 + d];
                            cm[mm] = fmaf(t, t, cm[mm]);
                        }
                    }
                }
            }
            __syncwarp();   // lane0's s_inp writes visible to whole warp
        }
    }

    if (ji == 0) {
#pragma unroll
        for (int mm = 0; mm < 8; mm++)
            g_cost[s_idx * BB + b0 + mrow + mm] = cm[mm];
    }
}

// ---------------------------------------------------------------------------
// Kernel 3: first-argmin over samples, gather chosen action.
// ---------------------------------------------------------------------------
__global__ __launch_bounds__(256) void select_kernel(float* __restrict__ out)
{
    int b = blockIdx.x * blockDim.x + threadIdx.x;
    if (b >= BB) return;
    float best = g_cost[b];
    int bi = 0;
#pragma unroll
    for (int s = 1; s < SSAMP; s++) {
        float c = g_cost[s * BB + b];
        if (c < best) { best = c; bi = s; }
    }
    const float* src = g_cand + (bi * BB + b) * 7;
#pragma unroll
    for (int a = 0; a < 7; a++) out[b * 7 + a] = src[a];
}

// ---------------------------------------------------------------------------
extern "C" void kernel_launch(void* const* d_in, const int* in_sizes, int n_in,
                              void* d_out, int out_size)
{
    (void)in_sizes; (void)n_in; (void)out_size;
    const float* state   = (const float*)d_in[0];
    const float* proprio = (const float*)d_in[1];
    const float* target  = (const float*)d_in[2];
    const float* noise   = (const float*)d_in[3];
    const float* pw1 = (const float*)d_in[4];
    const float* pb1 = (const float*)d_in[5];
    const float* pw2 = (const float*)d_in[6];
    const float* pb2 = (const float*)d_in[7];
    const float* w1  = (const float*)d_in[8];
    const float* b1  = (const float*)d_in[9];
    const float* w2  = (const float*)d_in[10];
    const float* b2  = (const float*)d_in[11];
    const float* w3  = (const float*)d_in[12];
    const float* b3  = (const float*)d_in[13];
    float* out = (float*)d_out;

    cudaFuncSetAttribute(rollout_kernel,
                         cudaFuncAttributeMaxDynamicSharedMemorySize, SMEM_BYTES);

    proposal_kernel<<<BB / 8, 256>>>(state, proprio, noise, pw1, pb1, pw2, pb2);
    rollout_kernel<<<(SSAMP * BB) / TILE_M, 256, SMEM_BYTES>>>(
        state, target, w1, b1, w2, b2, w3, b3);
    select_kernel<<<BB / 256, 256>>>(out);
}

// round 2
// speedup vs baseline: 1.0468x; 1.0468x over previous
#include <cuda_runtime.h>
#include <cstdint>

// Problem constants (fixed by setup_inputs)
#define BB     8192
#define SSAMP  8
#define HH     256
#define SD     9
#define AD     7
#define IN2    16
#define HOR    4
#define TILE_M 64
#define KT     32

// Scratch (device globals — no allocation allowed)
__device__ float g_cand[SSAMP * BB * AD];   // (S,B,7) clipped candidates
__device__ float g_cost[SSAMP * BB];        // (S,B) total rollout cost

// Shared-memory layout (floats) for rollout kernel
// s_w1:4096 | s_b1:256 | s_b2:256 | s_w3t:2304 | s_b3:16 | s_tgt:192 |
// s_inp:1024 | s_h:16384 | s_wt:3*8192  => 49104 floats = 196416 bytes
#define SMEM_FLOATS 49104
#define SMEM_BYTES  (SMEM_FLOATS * 4)

typedef unsigned long long u64;

struct F4 { float v[4]; };

__device__ __forceinline__ F4 ld4s(const float* p) {
    float4 t = *reinterpret_cast<const float4*>(p);
    F4 r; r.v[0] = t.x; r.v[1] = t.y; r.v[2] = t.z; r.v[3] = t.w;
    return r;
}

// ---- packed fp32x2 helpers (Blackwell paired-FP32 path, PTX-only) ----
__device__ __forceinline__ u64 dup2f(float x) {
    u64 r; asm("mov.b64 %0, {%1, %2};" : "=l"(r) : "f"(x), "f"(x)); return r;
}
__device__ __forceinline__ void fma2(u64& d, u64 a, u64 b) {
    asm("fma.rn.f32x2 %0, %1, %2, %3;" : "=l"(d) : "l"(a), "l"(b), "l"(d));
}
__device__ __forceinline__ float2 unpk(u64 x) {
    float2 f; asm("mov.b64 {%0, %1}, %2;" : "=f"(f.x), "=f"(f.y) : "l"(x)); return f;
}
__device__ __forceinline__ u64 relu2(u64 x) {
    float2 f = unpk(x);
    f.x = fmaxf(f.x, 0.0f); f.y = fmaxf(f.y, 0.0f);
    u64 r; asm("mov.b64 %0, {%1, %2};" : "=l"(r) : "f"(f.x), "f"(f.y)); return r;
}

__device__ __forceinline__ void cp16(float* smem_dst, const float* gsrc) {
    uint32_t d = (uint32_t)__cvta_generic_to_shared(smem_dst);
    asm volatile("cp.async.cg.shared.global [%0], [%1], 16;\n" :: "r"(d), "l"(gsrc));
}
__device__ __forceinline__ void cp_commit() {
    asm volatile("cp.async.commit_group;\n" ::);
}
__device__ __forceinline__ void cp_wait1() {
    asm volatile("cp.async.wait_group 1;\n" ::);
}
__device__ __forceinline__ void cp_wait0() {
    asm volatile("cp.async.wait_group 0;\n" ::);
}

// ---------------------------------------------------------------------------
// Kernel 1: action proposal. One warp per batch row b.
// ---------------------------------------------------------------------------
__global__ __launch_bounds__(256) void proposal_kernel(
    const float* __restrict__ state, const float* __restrict__ proprio,
    const float* __restrict__ noise,
    const float* __restrict__ pw1, const float* __restrict__ pb1,
    const float* __restrict__ pw2, const float* __restrict__ pb2)
{
    int warp = threadIdx.x >> 5, lane = threadIdx.x & 31;
    int b = blockIdx.x * 8 + warp;

    float h[8];
#pragma unroll
    for (int c = 0; c < 8; c++) h[c] = pb1[lane + 32 * c];
#pragma unroll
    for (int i = 0; i < 11; i++) {
        float xi = (i < 9) ? state[b * 9 + i] : proprio[b * 2 + (i - 9)];
#pragma unroll
        for (int c = 0; c < 8; c++)
            h[c] = fmaf(xi, pw1[i * 256 + lane + 32 * c], h[c]);
    }
#pragma unroll
    for (int c = 0; c < 8; c++) h[c] = fmaxf(h[c], 0.0f);

    float p[7];
#pragma unroll
    for (int a = 0; a < 7; a++) {
        float s = 0.0f;
#pragma unroll
        for (int c = 0; c < 8; c++)
            s = fmaf(h[c], pw2[(lane + 32 * c) * 7 + a], s);
        p[a] = s;
    }
#pragma unroll
    for (int off = 16; off >= 1; off >>= 1) {
#pragma unroll
        for (int a = 0; a < 7; a++)
            p[a] += __shfl_xor_sync(0xffffffffu, p[a], off);
    }

    if (lane < 7) {
        float base = tanhf(p[lane] + pb2[lane]);
#pragma unroll
        for (int s = 0; s < SSAMP; s++) {
            float v = base + 0.2f * noise[(s * BB + b) * 7 + lane];
            v = fminf(fmaxf(v, -1.0f), 1.0f);
            g_cand[(s * BB + b) * 7 + lane] = v;
        }
    }
}

// ---------------------------------------------------------------------------
// Kernel 2: rollout. 1 CTA = 64 samples. 256 threads, 8x8 register tile,
// accumulators packed as fp32x2 pairs along j. w2 streamed through smem
// (cp.async, TRIPLE-buffered 32-row tiles, one barrier per tile).
// ---------------------------------------------------------------------------
__global__ __launch_bounds__(256, 1) void rollout_kernel(
    const float* __restrict__ state, const float* __restrict__ target,
    const float* __restrict__ w1, const float* __restrict__ b1,
    const float* __restrict__ w2, const float* __restrict__ b2,
    const float* __restrict__ w3, const float* __restrict__ b3)
{
    extern __shared__ float smem[];
    float* s_w1  = smem;              // [16][256]
    float* s_b1  = s_w1 + 4096;       // [256]
    float* s_b2  = s_b1 + 256;        // [256]
    float* s_w3t = s_b2 + 256;        // [9][256]  (transposed w3)
    float* s_b3  = s_w3t + 2304;      // [16]
    float* s_tgt = s_b3 + 16;         // [64][3]
    float* s_inp = s_tgt + 192;       // [64][16]  cols 0..8=sim, 9..15=cand
    float* s_h   = s_inp + 1024;      // [64][256]
    float* s_wt  = s_h + 16384;       // [3][32][256]

    const int tid = threadIdx.x;
    const int sample0 = blockIdx.x * TILE_M;
    const int s_idx = sample0 / BB;
    const int b0 = sample0 % BB;

    // ---- kick off prefetch of w2 tile 0 into buffer 0 immediately ----
    {
        const float4* src = reinterpret_cast<const float4*>(w2);
        float4* dst = reinterpret_cast<float4*>(s_wt);
#pragma unroll
        for (int i = 0; i < 8; i++) {
            int idx = tid + i * 256;
            cp16(reinterpret_cast<float*>(dst + idx),
                 reinterpret_cast<const float*>(src + idx));
        }
        cp_commit();
    }

    // ---- cooperative init ----
    {
        const float4* w1v = reinterpret_cast<const float4*>(w1);
        float4* sw1v = reinterpret_cast<float4*>(s_w1);
        for (int i = tid; i < 1024; i += 256) sw1v[i] = w1v[i];
        s_b1[tid] = b1[tid];
        s_b2[tid] = b2[tid];
        for (int i = tid; i < 2304; i += 256) {
            int j = i / 9, d = i % 9;
            s_w3t[d * 256 + j] = w3[i];
        }
        if (tid < 9) s_b3[tid] = b3[tid];
        if (tid < 192) s_tgt[tid] = target[b0 * 3 + tid];
        for (int i = tid; i < 576; i += 256) {
            int m = i / 9, d = i % 9;
            s_inp[m * 16 + d] = state[(b0 + m) * 9 + d];
        }
        for (int i = tid; i < 448; i += 256) {
            int m = i / 7, a = i % 7;
            s_inp[m * 16 + 9 + a] = g_cand[(s_idx * BB + b0 + m) * 7 + a];
        }
    }
    __syncthreads();

    const int mi = tid >> 5;          // warp id 0..7
    const int ji = tid & 31;          // lane
    const int J0 = ji * 4;
    const int J1 = 128 + ji * 4;
    const int mrow = mi * 8;

    float cm[8];
#pragma unroll
    for (int mm = 0; mm < 8; mm++) cm[mm] = 0.0f;

    // packed accumulators: accp[mm][0..1] = J0 slice pairs, [2..3] = J1 slice
    u64 accp[8][4];

    int cur = 0;   // s_wt buffer holding the tile about to be consumed

    for (int step = 0; step < HOR; step++) {
        // ================= GEMM1: h1 = relu(inp @ w1 + b1) =================
        {
            ulonglong2 bA = *reinterpret_cast<const ulonglong2*>(s_b1 + J0);
            ulonglong2 bB = *reinterpret_cast<const ulonglong2*>(s_b1 + J1);
#pragma unroll
            for (int mm = 0; mm < 8; mm++) {
                accp[mm][0] = bA.x; accp[mm][1] = bA.y;
                accp[mm][2] = bB.x; accp[mm][3] = bB.y;
            }
#pragma unroll 2
            for (int k0 = 0; k0 < 16; k0 += 4) {
                ulonglong2 wA2[4], wB2[4];
#pragma unroll
                for (int t = 0; t < 4; t++) {
                    wA2[t] = *reinterpret_cast<const ulonglong2*>(s_w1 + (k0 + t) * 256 + J0);
                    wB2[t] = *reinterpret_cast<const ulonglong2*>(s_w1 + (k0 + t) * 256 + J1);
                }
#pragma unroll
                for (int mm = 0; mm < 8; mm++) {
                    F4 iv = ld4s(s_inp + (mrow + mm) * 16 + k0);
#pragma unroll
                    for (int t = 0; t < 4; t++) {
                        u64 hd = dup2f(iv.v[t]);
                        fma2(accp[mm][0], hd, wA2[t].x);
                        fma2(accp[mm][1], hd, wA2[t].y);
                        fma2(accp[mm][2], hd, wB2[t].x);
                        fma2(accp[mm][3], hd, wB2[t].y);
                    }
                }
            }
            // relu + store h1 (warp-private rows)
#pragma unroll
            for (int mm = 0; mm < 8; mm++) {
                float2 a0 = unpk(accp[mm][0]), a1 = unpk(accp[mm][1]);
                float2 a2 = unpk(accp[mm][2]), a3 = unpk(accp[mm][3]);
                float4 st0, st1;
                st0.x = fmaxf(a0.x, 0.0f); st0.y = fmaxf(a0.y, 0.0f);
                st0.z = fmaxf(a1.x, 0.0f); st0.w = fmaxf(a1.y, 0.0f);
                st1.x = fmaxf(a2.x, 0.0f); st1.y = fmaxf(a2.y, 0.0f);
                st1.z = fmaxf(a3.x, 0.0f); st1.w = fmaxf(a3.y, 0.0f);
                *reinterpret_cast<float4*>(&s_h[(mrow + mm) * 256 + J0]) = st0;
                *reinterpret_cast<float4*>(&s_h[(mrow + mm) * 256 + J1]) = st1;
            }
        }

        // ================= GEMM2: z2 = h1 @ w2 + b2 (k-tiled) ==============
        {
            ulonglong2 bA = *reinterpret_cast<const ulonglong2*>(s_b2 + J0);
            ulonglong2 bB = *reinterpret_cast<const ulonglong2*>(s_b2 + J1);
#pragma unroll
            for (int mm = 0; mm < 8; mm++) {
                accp[mm][0] = bA.x; accp[mm][1] = bA.y;
                accp[mm][2] = bB.x; accp[mm][3] = bB.y;
            }

            for (int kt = 0; kt < 8; kt++) {
                int nxt = cur + 1; if (nxt == 3) nxt = 0;
                bool more = (kt < 7) || (step < HOR - 1);
                if (more) {
                    // prefetch next tile: wraps to tile 0 of the next step
                    int ntile = (kt + 1) & 7;
                    const float4* src = reinterpret_cast<const float4*>(w2 + ntile * KT * 256);
                    float4* dst = reinterpret_cast<float4*>(s_wt + nxt * 8192);
#pragma unroll
                    for (int i = 0; i < 8; i++) {
                        int idx = tid + i * 256;
                        cp16(reinterpret_cast<float*>(dst + idx),
                             reinterpret_cast<const float*>(src + idx));
                    }
                    cp_commit();
                    cp_wait1();
                } else {
                    cp_wait0();
                }
                __syncthreads();   // tile in buf 'cur' visible to all

                const float* W = s_wt + cur * 8192;
                const float* Hbase = s_h + mrow * 256 + kt * KT;
#pragma unroll 2
                for (int kk = 0; kk < KT; kk += 4) {
                    ulonglong2 wA2[4], wB2[4];
#pragma unroll
                    for (int t = 0; t < 4; t++) {
                        wA2[t] = *reinterpret_cast<const ulonglong2*>(W + (kk + t) * 256 + J0);
                        wB2[t] = *reinterpret_cast<const ulonglong2*>(W + (kk + t) * 256 + J1);
                    }
#pragma unroll
                    for (int mm = 0; mm < 8; mm++) {
                        F4 hv = ld4s(Hbase + mm * 256 + kk);
#pragma unroll
                        for (int t = 0; t < 4; t++) {
                            u64 hd = dup2f(hv.v[t]);
                            fma2(accp[mm][0], hd, wA2[t].x);
                            fma2(accp[mm][1], hd, wA2[t].y);
                            fma2(accp[mm][2], hd, wB2[t].x);
                            fma2(accp[mm][3], hd, wB2[t].y);
                        }
                    }
                }
                cur = nxt;
                // NOTE: no second barrier — triple buffering guarantees the
                // buffer being prefetched was last read two tiles ago, and all
                // warps passed the barrier above after that read completed.
            }
        }

        // ============ GEMM3: sim = relu(z2) @ w3 + b3 ; cost accum =========
        {
#pragma unroll
            for (int mm = 0; mm < 8; mm++)
#pragma unroll
                for (int p = 0; p < 4; p++) accp[mm][p] = relu2(accp[mm][p]);

            for (int d = 0; d < 9; d++) {
                ulonglong2 wA2 = *reinterpret_cast<const ulonglong2*>(s_w3t + d * 256 + J0);
                ulonglong2 wB2 = *reinterpret_cast<const ulonglong2*>(s_w3t + d * 256 + J1);
                float pd[8];
#pragma unroll
                for (int mm = 0; mm < 8; mm++) {
                    u64 p = 0ULL;  // (+0.0f, +0.0f)
                    fma2(p, accp[mm][0], wA2.x);
                    fma2(p, accp[mm][1], wA2.y);
                    fma2(p, accp[mm][2], wB2.x);
                    fma2(p, accp[mm][3], wB2.y);
                    float2 f = unpk(p);
                    pd[mm] = f.x + f.y;
                }
#pragma unroll
                for (int off = 16; off >= 1; off >>= 1) {
#pragma unroll
                    for (int mm = 0; mm < 8; mm++)
                        pd[mm] += __shfl_xor_sync(0xffffffffu, pd[mm], off);
                }
                if (ji == 0) {
#pragma unroll
                    for (int mm = 0; mm < 8; mm++) {
                        float sv = pd[mm] + s_b3[d];
                        s_inp[(mrow + mm) * 16 + d] = sv;
                        if (d < 3) {
                            float t = sv - s_tgt[(mrow + mm) * 3 + d];
                            cm[mm] = fmaf(t, t, cm[mm]);
                        }
                    }
                }
            }
            __syncwarp();   // lane0's s_inp writes visible to whole warp
        }
    }

    if (ji == 0) {
#pragma unroll
        for (int mm = 0; mm < 8; mm++)
            g_cost[s_idx * BB + b0 + mrow + mm] = cm[mm];
    }
}

// ---------------------------------------------------------------------------
// Kernel 3: first-argmin over samples, gather chosen action.
// ---------------------------------------------------------------------------
__global__ __launch_bounds__(256) void select_kernel(float* __restrict__ out)
{
    int b = blockIdx.x * blockDim.x + threadIdx.x;
    if (b >= BB) return;
    float best = g_cost[b];
    int bi = 0;
#pragma unroll
    for (int s = 1; s < SSAMP; s++) {
        float c = g_cost[s * BB + b];
        if (c < best) { best = c; bi = s; }
    }
    const float* src = g_cand + (bi * BB + b) * 7;
#pragma unroll
    for (int a = 0; a < 7; a++) out[b * 7 + a] = src[a];
}

// ---------------------------------------------------------------------------
extern "C" void kernel_launch(void* const* d_in, const int* in_sizes, int n_in,
                              void* d_out, int out_size)
{
    (void)in_sizes; (void)n_in; (void)out_size;
    const float* state   = (const float*)d_in[0];
    const float* proprio = (const float*)d_in[1];
    const float* target  = (const float*)d_in[2];
    const float* noise   = (const float*)d_in[3];
    const float* pw1 = (const float*)d_in[4];
    const float* pb1 = (const float*)d_in[5];
    const float* pw2 = (const float*)d_in[6];
    const float* pb2 = (const float*)d_in[7];
    const float* w1  = (const float*)d_in[8];
    const float* b1  = (const float*)d_in[9];
    const float* w2  = (const float*)d_in[10];
    const float* b2  = (const float*)d_in[11];
    const float* w3  = (const float*)d_in[12];
    const float* b3  = (const float*)d_in[13];
    float* out = (float*)d_out;

    cudaFuncSetAttribute(rollout_kernel,
                         cudaFuncAttributeMaxDynamicSharedMemorySize, SMEM_BYTES);

    proposal_kernel<<<BB / 8, 256>>>(state, proprio, noise, pw1, pb1, pw2, pb2);
    rollout_kernel<<<(SSAMP * BB) / TILE_M, 256, SMEM_BYTES>>>(
        state, target, w1, b1, w2, b2, w3, b3);
    select_kernel<<<BB / 256, 256>>>(out);
}

// round 3
// speedup vs baseline: 1.0485x; 1.0016x over previous
#include <cuda_runtime.h>
#include <cstdint>

// Problem constants (fixed by setup_inputs)
#define BB     8192
#define SSAMP  8
#define HH     256
#define SD     9
#define AD     7
#define IN2    16
#define HOR    4
#define TILE_M 64
#define KT     32

// Scratch (device globals — no allocation allowed)
__device__ float g_cand[SSAMP * BB * AD];   // (S,B,7) clipped candidates
__device__ float g_cost[SSAMP * BB];        // (S,B) total rollout cost

// Shared-memory layout (floats) for rollout kernel
// s_w1:4096 | s_b1:256 | s_b2:256 | s_w3t:2304 | s_b3:16 | s_tgt:192 |
// s_inp:1024 | s_h:16384 | s_wt:3*8192  => 49104 floats = 196416 bytes
#define SMEM_FLOATS 49104
#define SMEM_BYTES  (SMEM_FLOATS * 4)

typedef unsigned long long u64;

struct F4 { float v[4]; };

__device__ __forceinline__ F4 ld4s(const float* p) {
    float4 t = *reinterpret_cast<const float4*>(p);
    F4 r; r.v[0] = t.x; r.v[1] = t.y; r.v[2] = t.z; r.v[3] = t.w;
    return r;
}

// ---- packed fp32x2 helpers (Blackwell paired-FP32 path, PTX-only) ----
__device__ __forceinline__ u64 dup2f(float x) {
    u64 r; asm("mov.b64 %0, {%1, %2};" : "=l"(r) : "f"(x), "f"(x)); return r;
}
__device__ __forceinline__ void fma2(u64& d, u64 a, u64 b) {
    asm("fma.rn.f32x2 %0, %1, %2, %3;" : "=l"(d) : "l"(a), "l"(b), "l"(d));
}
__device__ __forceinline__ float2 unpk(u64 x) {
    float2 f; asm("mov.b64 {%0, %1}, %2;" : "=f"(f.x), "=f"(f.y) : "l"(x)); return f;
}
__device__ __forceinline__ u64 relu2(u64 x) {
    float2 f = unpk(x);
    f.x = fmaxf(f.x, 0.0f); f.y = fmaxf(f.y, 0.0f);
    u64 r; asm("mov.b64 %0, {%1, %2};" : "=l"(r) : "f"(f.x), "f"(f.y)); return r;
}

__device__ __forceinline__ void cp16(float* smem_dst, const float* gsrc) {
    uint32_t d = (uint32_t)__cvta_generic_to_shared(smem_dst);
    asm volatile("cp.async.cg.shared.global [%0], [%1], 16;\n" :: "r"(d), "l"(gsrc));
}
__device__ __forceinline__ void cp_commit() {
    asm volatile("cp.async.commit_group;\n" ::);
}
__device__ __forceinline__ void cp_wait1() {
    asm volatile("cp.async.wait_group 1;\n" ::);
}
__device__ __forceinline__ void cp_wait0() {
    asm volatile("cp.async.wait_group 0;\n" ::);
}

// ---------------------------------------------------------------------------
// Kernel 1: action proposal. One warp per batch row b.
// ---------------------------------------------------------------------------
__global__ __launch_bounds__(256) void proposal_kernel(
    const float* __restrict__ state, const float* __restrict__ proprio,
    const float* __restrict__ noise,
    const float* __restrict__ pw1, const float* __restrict__ pb1,
    const float* __restrict__ pw2, const float* __restrict__ pb2)
{
    int warp = threadIdx.x >> 5, lane = threadIdx.x & 31;
    int b = blockIdx.x * 8 + warp;

    float h[8];
#pragma unroll
    for (int c = 0; c < 8; c++) h[c] = pb1[lane + 32 * c];
#pragma unroll
    for (int i = 0; i < 11; i++) {
        float xi = (i < 9) ? state[b * 9 + i] : proprio[b * 2 + (i - 9)];
#pragma unroll
        for (int c = 0; c < 8; c++)
            h[c] = fmaf(xi, pw1[i * 256 + lane + 32 * c], h[c]);
    }
#pragma unroll
    for (int c = 0; c < 8; c++) h[c] = fmaxf(h[c], 0.0f);

    float p[7];
#pragma unroll
    for (int a = 0; a < 7; a++) {
        float s = 0.0f;
#pragma unroll
        for (int c = 0; c < 8; c++)
            s = fmaf(h[c], pw2[(lane + 32 * c) * 7 + a], s);
        p[a] = s;
    }
#pragma unroll
    for (int off = 16; off >= 1; off >>= 1) {
#pragma unroll
        for (int a = 0; a < 7; a++)
            p[a] += __shfl_xor_sync(0xffffffffu, p[a], off);
    }

    if (lane < 7) {
        float base = tanhf(p[lane] + pb2[lane]);
#pragma unroll
        for (int s = 0; s < SSAMP; s++) {
            float v = base + 0.2f * noise[(s * BB + b) * 7 + lane];
            v = fminf(fmaxf(v, -1.0f), 1.0f);
            g_cand[(s * BB + b) * 7 + lane] = v;
        }
    }
}

// ---------------------------------------------------------------------------
// Kernel 2: rollout. 1 CTA = 64 samples. 256 threads, 8x8 register tile,
// accumulators packed as fp32x2 pairs along j. w2 streamed through smem
// (cp.async, TRIPLE-buffered 32-row tiles, one barrier per tile).
// ---------------------------------------------------------------------------
__global__ __launch_bounds__(256, 1) void rollout_kernel(
    const float* __restrict__ state, const float* __restrict__ target,
    const float* __restrict__ w1, const float* __restrict__ b1,
    const float* __restrict__ w2, const float* __restrict__ b2,
    const float* __restrict__ w3, const float* __restrict__ b3)
{
    extern __shared__ float smem[];
    float* s_w1  = smem;              // [16][256]
    float* s_b1  = s_w1 + 4096;       // [256]
    float* s_b2  = s_b1 + 256;        // [256]
    float* s_w3t = s_b2 + 256;        // [9][256]  (transposed w3)
    float* s_b3  = s_w3t + 2304;      // [16]
    float* s_tgt = s_b3 + 16;         // [64][3]
    float* s_inp = s_tgt + 192;       // [64][16]  cols 0..8=sim, 9..15=cand
    float* s_h   = s_inp + 1024;      // [64][256]
    float* s_wt  = s_h + 16384;       // [3][32][256]

    const int tid = threadIdx.x;
    const int sample0 = blockIdx.x * TILE_M;
    const int s_idx = sample0 / BB;
    const int b0 = sample0 % BB;

    // ---- kick off prefetch of w2 tile 0 into buffer 0 immediately ----
    {
        const float4* src = reinterpret_cast<const float4*>(w2);
        float4* dst = reinterpret_cast<float4*>(s_wt);
#pragma unroll
        for (int i = 0; i < 8; i++) {
            int idx = tid + i * 256;
            cp16(reinterpret_cast<float*>(dst + idx),
                 reinterpret_cast<const float*>(src + idx));
        }
        cp_commit();
    }

    // ---- cooperative init ----
    {
        const float4* w1v = reinterpret_cast<const float4*>(w1);
        float4* sw1v = reinterpret_cast<float4*>(s_w1);
        for (int i = tid; i < 1024; i += 256) sw1v[i] = w1v[i];
        s_b1[tid] = b1[tid];
        s_b2[tid] = b2[tid];
        for (int i = tid; i < 2304; i += 256) {
            int j = i / 9, d = i % 9;
            s_w3t[d * 256 + j] = w3[i];
        }
        if (tid < 9) s_b3[tid] = b3[tid];
        if (tid < 192) s_tgt[tid] = target[b0 * 3 + tid];
        for (int i = tid; i < 576; i += 256) {
            int m = i / 9, d = i % 9;
            s_inp[m * 16 + d] = state[(b0 + m) * 9 + d];
        }
        for (int i = tid; i < 448; i += 256) {
            int m = i / 7, a = i % 7;
            s_inp[m * 16 + 9 + a] = g_cand[(s_idx * BB + b0 + m) * 7 + a];
        }
    }
    __syncthreads();

    const int mi = tid >> 5;          // warp id 0..7
    const int ji = tid & 31;          // lane
    const int J0 = ji * 4;
    const int J1 = 128 + ji * 4;
    const int mrow = mi * 8;

    float cm[8];
#pragma unroll
    for (int mm = 0; mm < 8; mm++) cm[mm] = 0.0f;

    // packed accumulators: accp[mm][0..1] = J0 slice pairs, [2..3] = J1 slice
    u64 accp[8][4];

    int cur = 0;   // s_wt buffer holding the tile about to be consumed

    for (int step = 0; step < HOR; step++) {
        // ================= GEMM1: h1 = relu(inp @ w1 + b1) =================
        {
            ulonglong2 bA = *reinterpret_cast<const ulonglong2*>(s_b1 + J0);
            ulonglong2 bB = *reinterpret_cast<const ulonglong2*>(s_b1 + J1);
#pragma unroll
            for (int mm = 0; mm < 8; mm++) {
                accp[mm][0] = bA.x; accp[mm][1] = bA.y;
                accp[mm][2] = bB.x; accp[mm][3] = bB.y;
            }
#pragma unroll 2
            for (int k0 = 0; k0 < 16; k0 += 4) {
                ulonglong2 wA2[4], wB2[4];
#pragma unroll
                for (int t = 0; t < 4; t++) {
                    wA2[t] = *reinterpret_cast<const ulonglong2*>(s_w1 + (k0 + t) * 256 + J0);
                    wB2[t] = *reinterpret_cast<const ulonglong2*>(s_w1 + (k0 + t) * 256 + J1);
                }
#pragma unroll
                for (int mm = 0; mm < 8; mm++) {
                    F4 iv = ld4s(s_inp + (mrow + mm) * 16 + k0);
#pragma unroll
                    for (int t = 0; t < 4; t++) {
                        u64 hd = dup2f(iv.v[t]);
                        fma2(accp[mm][0], hd, wA2[t].x);
                        fma2(accp[mm][1], hd, wA2[t].y);
                        fma2(accp[mm][2], hd, wB2[t].x);
                        fma2(accp[mm][3], hd, wB2[t].y);
                    }
                }
            }
            // relu + store h1 (warp-private rows)
#pragma unroll
            for (int mm = 0; mm < 8; mm++) {
                float2 a0 = unpk(accp[mm][0]), a1 = unpk(accp[mm][1]);
                float2 a2 = unpk(accp[mm][2]), a3 = unpk(accp[mm][3]);
                float4 st0, st1;
                st0.x = fmaxf(a0.x, 0.0f); st0.y = fmaxf(a0.y, 0.0f);
                st0.z = fmaxf(a1.x, 0.0f); st0.w = fmaxf(a1.y, 0.0f);
                st1.x = fmaxf(a2.x, 0.0f); st1.y = fmaxf(a2.y, 0.0f);
                st1.z = fmaxf(a3.x, 0.0f); st1.w = fmaxf(a3.y, 0.0f);
                *reinterpret_cast<float4*>(&s_h[(mrow + mm) * 256 + J0]) = st0;
                *reinterpret_cast<float4*>(&s_h[(mrow + mm) * 256 + J1]) = st1;
            }
        }

        // ================= GEMM2: z2 = h1 @ w2 + b2 (k-tiled) ==============
        {
            ulonglong2 bA = *reinterpret_cast<const ulonglong2*>(s_b2 + J0);
            ulonglong2 bB = *reinterpret_cast<const ulonglong2*>(s_b2 + J1);
#pragma unroll
            for (int mm = 0; mm < 8; mm++) {
                accp[mm][0] = bA.x; accp[mm][1] = bA.y;
                accp[mm][2] = bB.x; accp[mm][3] = bB.y;
            }

            for (int kt = 0; kt < 8; kt++) {
                int nxt = cur + 1; if (nxt == 3) nxt = 0;
                bool more = (kt < 7) || (step < HOR - 1);
                if (more) {
                    // prefetch next tile: wraps to tile 0 of the next step
                    int ntile = (kt + 1) & 7;
                    const float4* src = reinterpret_cast<const float4*>(w2 + ntile * KT * 256);
                    float4* dst = reinterpret_cast<float4*>(s_wt + nxt * 8192);
#pragma unroll
                    for (int i = 0; i < 8; i++) {
                        int idx = tid + i * 256;
                        cp16(reinterpret_cast<float*>(dst + idx),
                             reinterpret_cast<const float*>(src + idx));
                    }
                    cp_commit();
                    cp_wait1();
                } else {
                    cp_wait0();
                }
                __syncthreads();   // tile in buf 'cur' visible to all

                const float* W = s_wt + cur * 8192;
                const float* Hbase = s_h + mrow * 256 + kt * KT;
#pragma unroll 2
                for (int kk = 0; kk < KT; kk += 4) {
                    ulonglong2 wA2[4], wB2[4];
#pragma unroll
                    for (int t = 0; t < 4; t++) {
                        wA2[t] = *reinterpret_cast<const ulonglong2*>(W + (kk + t) * 256 + J0);
                        wB2[t] = *reinterpret_cast<const ulonglong2*>(W + (kk + t) * 256 + J1);
                    }
#pragma unroll
                    for (int mm = 0; mm < 8; mm++) {
                        F4 hv = ld4s(Hbase + mm * 256 + kk);
#pragma unroll
                        for (int t = 0; t < 4; t++) {
                            u64 hd = dup2f(hv.v[t]);
                            fma2(accp[mm][0], hd, wA2[t].x);
                            fma2(accp[mm][1], hd, wA2[t].y);
                            fma2(accp[mm][2], hd, wB2[t].x);
                            fma2(accp[mm][3], hd, wB2[t].y);
                        }
                    }
                }
                cur = nxt;
                // NOTE: no second barrier — triple buffering guarantees the
                // buffer being prefetched was last read two tiles ago, and all
                // warps passed the barrier above after that read completed.
            }
        }

        // ============ GEMM3: sim = relu(z2) @ w3 + b3 ; cost accum =========
        {
#pragma unroll
            for (int mm = 0; mm < 8; mm++)
#pragma unroll
                for (int p = 0; p < 4; p++) accp[mm][p] = relu2(accp[mm][p]);

            for (int d = 0; d < 9; d++) {
                ulonglong2 wA2 = *reinterpret_cast<const ulonglong2*>(s_w3t + d * 256 + J0);
                ulonglong2 wB2 = *reinterpret_cast<const ulonglong2*>(s_w3t + d * 256 + J1);
                float pd[8];
#pragma unroll
                for (int mm = 0; mm < 8; mm++) {
                    u64 p = 0ULL;  // (+0.0f, +0.0f)
                    fma2(p, accp[mm][0], wA2.x);
                    fma2(p, accp[mm][1], wA2.y);
                    fma2(p, accp[mm][2], wB2.x);
                    fma2(p, accp[mm][3], wB2.y);
                    float2 f = unpk(p);
                    pd[mm] = f.x + f.y;
                }
#pragma unroll
                for (int off = 16; off >= 1; off >>= 1) {
#pragma unroll
                    for (int mm = 0; mm < 8; mm++)
                        pd[mm] += __shfl_xor_sync(0xffffffffu, pd[mm], off);
                }
                if (ji == 0) {
#pragma unroll
                    for (int mm = 0; mm < 8; mm++) {
                        float sv = pd[mm] + s_b3[d];
                        s_inp[(mrow + mm) * 16 + d] = sv;
                        if (d < 3) {
                            float t = sv - s_tgt[(mrow + mm) * 3 + d];
                            cm[mm] = fmaf(t, t, cm[mm]);
                        }
                    }
                }
            }
            __syncwarp();   // lane0's s_inp writes visible to whole warp
        }
    }

    if (ji == 0) {
#pragma unroll
        for (int mm = 0; mm < 8; mm++)
            g_cost[s_idx * BB + b0 + mrow + mm] = cm[mm];
    }
}

// ---------------------------------------------------------------------------
// Kernel 3: first-argmin over samples, gather chosen action.
// ---------------------------------------------------------------------------
__global__ __launch_bounds__(256) void select_kernel(float* __restrict__ out)
{
    int b = blockIdx.x * blockDim.x + threadIdx.x;
    if (b >= BB) return;
    float best = g_cost[b];
    int bi = 0;
#pragma unroll
    for (int s = 1; s < SSAMP; s++) {
        float c = g_cost[s * BB + b];
        if (c < best) { best = c; bi = s; }
    }
    const float* src = g_cand + (bi * BB + b) * 7;
#pragma unroll
    for (int a = 0; a < 7; a++) out[b * 7 + a] = src[a];
}

// ---------------------------------------------------------------------------
extern "C" void kernel_launch(void* const* d_in, const int* in_sizes, int n_in,
                              void* d_out, int out_size)
{
    (void)in_sizes; (void)n_in; (void)out_size;
    const float* state   = (const float*)d_in[0];
    const float* proprio = (const float*)d_in[1];
    const float* target  = (const float*)d_in[2];
    const float* noise   = (const float*)d_in[3];
    const float* pw1 = (const float*)d_in[4];
    const float* pb1 = (const float*)d_in[5];
    const float* pw2 = (const float*)d_in[6];
    const float* pb2 = (const float*)d_in[7];
    const float* w1  = (const float*)d_in[8];
    const float* b1  = (const float*)d_in[9];
    const float* w2  = (const float*)d_in[10];
    const float* b2  = (const float*)d_in[11];
    const float* w3  = (const float*)d_in[12];
    const float* b3  = (const float*)d_in[13];
    float* out = (float*)d_out;

    cudaFuncSetAttribute(rollout_kernel,
                         cudaFuncAttributeMaxDynamicSharedMemorySize, SMEM_BYTES);

    proposal_kernel<<<BB / 8, 256>>>(state, proprio, noise, pw1, pb1, pw2, pb2);
    rollout_kernel<<<(SSAMP * BB) / TILE_M, 256, SMEM_BYTES>>>(
        state, target, w1, b1, w2, b2, w3, b3);
    select_kernel<<<BB / 256, 256>>>(out);
}